// round 1
// baseline (speedup 1.0000x reference)
#include <cuda_runtime.h>
#include <cuda_bf16.h>

#define LDIM 4096
#define BDIM 32
#define CIN  64
#define ODIM 128
#define KDIM 9

// Scratch (allocation-free rule: __device__ globals)
__device__ float g_xs[BDIM * LDIM];      // channel-reduced x: [B][L]
__device__ float g_wcn[ODIM * KDIM];     // normalized weight_coeff
__device__ float g_evinv;                // 1 / ||err_vector||

// ---------------------------------------------------------------------------
// Kernel A: xs[b][l] = sum_i x[b,i,l]   (float4 over l)
// grid: BDIM*LDIM/4/256 = 128 blocks x 256 threads
// ---------------------------------------------------------------------------
__global__ __launch_bounds__(256) void reduce_x_kernel(const float* __restrict__ x) {
    int t  = blockIdx.x * blockDim.x + threadIdx.x;   // 0 .. B*L/4-1
    int b  = t / (LDIM / 4);
    int l4 = t % (LDIM / 4);
    const float4* xp = reinterpret_cast<const float4*>(x) +
                       (size_t)b * CIN * (LDIM / 4) + l4;
    float4 acc = make_float4(0.f, 0.f, 0.f, 0.f);
#pragma unroll 8
    for (int i = 0; i < CIN; ++i) {
        float4 v = xp[i * (LDIM / 4)];
        acc.x += v.x; acc.y += v.y; acc.z += v.z; acc.w += v.w;
    }
    reinterpret_cast<float4*>(g_xs)[b * (LDIM / 4) + l4] = acc;
}

// ---------------------------------------------------------------------------
// Kernel B: normalize err_vector (global L2) and weight_coeff rows (L2 over K)
// 1 block x 256 threads
// ---------------------------------------------------------------------------
__global__ __launch_bounds__(256) void prep_kernel(const float* __restrict__ wc,
                                                   const float* __restrict__ ev) {
    __shared__ float red[256];
    int t = threadIdx.x;
    float ssq = 0.f;
    for (int i = t; i < LDIM; i += 256) { float v = ev[i]; ssq += v * v; }
    red[t] = ssq;
    __syncthreads();
    for (int s = 128; s > 0; s >>= 1) {
        if (t < s) red[t] += red[t + s];
        __syncthreads();
    }
    if (t == 0) g_evinv = rsqrtf(red[0]);

    if (t < ODIM) {
        float w[KDIM];
        float n = 0.f;
#pragma unroll
        for (int k = 0; k < KDIM; ++k) { w[k] = wc[t * KDIM + k]; n += w[k] * w[k]; }
        float inv = rsqrtf(n);
#pragma unroll
        for (int k = 0; k < KDIM; ++k) g_wcn[t * KDIM + k] = w[k] * inv;
    }
}

// ---------------------------------------------------------------------------
// Kernel C: out[b,o,l] = ev[l]*evinv * sum_k wcn[o,k]*xs[b, idx[k,l]] + bias[o]
// grid: (4 l-tiles of 1024, 32 b), 256 threads, 4 consecutive l per thread
// ---------------------------------------------------------------------------
__global__ __launch_bounds__(256) void gmconv_main_kernel(
    const int*   __restrict__ idxm,
    const float* __restrict__ ev,
    const float* __restrict__ bias,
    float*       __restrict__ out) {

    __shared__ float s_xs[LDIM];            // 16 KB: xs[b][:]
    __shared__ float s_wc[ODIM * KDIM];     // 4.6 KB
    __shared__ float s_bias[ODIM];

    const int b    = blockIdx.y;
    const int tile = blockIdx.x;            // 0..3
    const int t    = threadIdx.x;

    // stage xs[b] and normalized weights into smem
    {
        float4*       s4 = reinterpret_cast<float4*>(s_xs);
        const float4* g4 = reinterpret_cast<const float4*>(g_xs + b * LDIM);
        for (int i = t; i < LDIM / 4; i += 256) s4[i] = g4[i];
        for (int i = t; i < ODIM * KDIM; i += 256) s_wc[i] = g_wcn[i];
        if (t < ODIM) s_bias[t] = bias[t];
    }
    __syncthreads();

    const int l = tile * 1024 + t * 4;
    const float evinv = g_evinv;
    float4 e4 = *reinterpret_cast<const float4*>(ev + l);
    const float ex = e4.x * evinv, ey = e4.y * evinv,
                ez = e4.z * evinv, ew = e4.w * evinv;

    // gather 9 neighbors per lane (from smem), pre-scale by ev[l]/||ev||
    float gx[KDIM], gy[KDIM], gz[KDIM], gw[KDIM];
#pragma unroll
    for (int k = 0; k < KDIM; ++k) {
        int4 id = *reinterpret_cast<const int4*>(idxm + k * LDIM + l);
        gx[k] = s_xs[id.x] * ex;
        gy[k] = s_xs[id.y] * ey;
        gz[k] = s_xs[id.z] * ez;
        gw[k] = s_xs[id.w] * ew;
    }

    float* outp = out + ((size_t)b * ODIM) * LDIM + l;
#pragma unroll 4
    for (int o = 0; o < ODIM; ++o) {
        const float bo = s_bias[o];
        float ax = bo, ay = bo, az = bo, aw = bo;
#pragma unroll
        for (int k = 0; k < KDIM; ++k) {
            const float w = s_wc[o * KDIM + k];   // smem broadcast
            ax = fmaf(w, gx[k], ax);
            ay = fmaf(w, gy[k], ay);
            az = fmaf(w, gz[k], az);
            aw = fmaf(w, gw[k], aw);
        }
        *reinterpret_cast<float4*>(outp + (size_t)o * LDIM) =
            make_float4(ax, ay, az, aw);          // coalesced across warp
    }
}

// ---------------------------------------------------------------------------
extern "C" void kernel_launch(void* const* d_in, const int* in_sizes, int n_in,
                              void* d_out, int out_size) {
    const float* x    = nullptr;
    const float* wc   = nullptr;
    const float* ev   = nullptr;
    const float* bias = nullptr;
    const int*   idxm = nullptr;

    for (int i = 0; i < n_in; ++i) {
        switch (in_sizes[i]) {
            case BDIM * CIN * LDIM: x    = (const float*)d_in[i]; break;  // 8388608
            case ODIM * KDIM:       wc   = (const float*)d_in[i]; break;  // 1152
            case LDIM:              ev   = (const float*)d_in[i]; break;  // 4096
            case ODIM:              bias = (const float*)d_in[i]; break;  // 128
            case KDIM * LDIM:       idxm = (const int*)  d_in[i]; break;  // 36864
            default: break;
        }
    }

    float* out = (float*)d_out;

    reduce_x_kernel<<<(BDIM * LDIM / 4) / 256, 256>>>(x);
    prep_kernel<<<1, 256>>>(wc, ev);
    gmconv_main_kernel<<<dim3(4, BDIM), 256>>>(idxm, ev, bias, out);
}

// round 2
// speedup vs baseline: 1.6023x; 1.6023x over previous
#include <cuda_runtime.h>
#include <cuda_bf16.h>

#define LDIM 4096
#define BDIM 32
#define CIN  64
#define ODIM 128
#define KDIM 9
#define CCHUNKS 4               // split-K chunks over channel dim
#define CPER   (CIN / CCHUNKS)  // 16 channels per chunk

// Scratch (allocation-free rule: __device__ globals)
__device__ float g_part[CCHUNKS * BDIM * LDIM]; // partial channel sums, 2 MB
__device__ float g_wcn[ODIM * KDIM];            // normalized weight_coeff
__device__ float g_evinv;                       // 1 / ||err_vector||

// ---------------------------------------------------------------------------
// Kernel A: split-K channel reduction (512 blocks) + prep (block 512)
//   blocks 0..511: g_part[cc][b][l] = sum_{i in chunk cc} x[b,i,l]
//   block 512:     normalize err_vector (global L2) + weight_coeff rows
// ---------------------------------------------------------------------------
__global__ __launch_bounds__(256) void reduce_prep_kernel(
    const float* __restrict__ x,
    const float* __restrict__ wc,
    const float* __restrict__ ev) {

    const int bx = blockIdx.x;
    const int t  = threadIdx.x;

    if (bx < BDIM * 4 * CCHUNKS) {             // 512 reduce blocks
        const int b   = bx >> 4;               // 0..31
        const int sub = bx & 15;
        const int lt  = sub >> 2;              // l-tile 0..3 (256 float4 each)
        const int cc  = sub & 3;               // channel chunk 0..3
        const int l4  = lt * 256 + t;          // 0..1023

        const float4* xp = reinterpret_cast<const float4*>(x) +
                           ((size_t)b * CIN + cc * CPER) * (LDIM / 4) + l4;
        float4 acc = make_float4(0.f, 0.f, 0.f, 0.f);
#pragma unroll
        for (int i = 0; i < CPER; ++i) {
            float4 v = __ldg(xp + i * (LDIM / 4));
            acc.x += v.x; acc.y += v.y; acc.z += v.z; acc.w += v.w;
        }
        reinterpret_cast<float4*>(g_part)[(cc * BDIM + b) * (LDIM / 4) + l4] = acc;
        return;
    }

    // ---- prep block ----
    __shared__ float red[256];
    float ssq = 0.f;
    for (int i = t; i < LDIM; i += 256) { float v = ev[i]; ssq += v * v; }
    red[t] = ssq;
    __syncthreads();
    for (int s = 128; s > 0; s >>= 1) {
        if (t < s) red[t] += red[t + s];
        __syncthreads();
    }
    if (t == 0) g_evinv = rsqrtf(red[0]);

    if (t < ODIM) {
        float w[KDIM];
        float n = 0.f;
#pragma unroll
        for (int k = 0; k < KDIM; ++k) { w[k] = wc[t * KDIM + k]; n += w[k] * w[k]; }
        float inv = rsqrtf(n);
#pragma unroll
        for (int k = 0; k < KDIM; ++k) g_wcn[t * KDIM + k] = w[k] * inv;
    }
}

// ---------------------------------------------------------------------------
// Kernel B: out[b,o,l] = ev[l]/||ev|| * sum_k wcn[o,k]*xs[b, idx[k,l]] + bias[o]
// grid: (4 l-tiles, 32 b, 2 o-chunks of 64) = 256 blocks, 256 threads
// Each block stages full xs[b] (combining the 4 split-K partials) in smem.
// ---------------------------------------------------------------------------
__global__ __launch_bounds__(256) void gmconv_main_kernel(
    const int*   __restrict__ idxm,
    const float* __restrict__ ev,
    const float* __restrict__ bias,
    float*       __restrict__ out) {

    __shared__ float s_xs[LDIM];                 // 16 KB
    __shared__ float s_wc[(ODIM / 2) * KDIM];    // 64*9 floats
    __shared__ float s_bias[ODIM / 2];

    const int tile = blockIdx.x;                 // 0..3
    const int b    = blockIdx.y;                 // 0..31
    const int oc   = blockIdx.z;                 // 0..1
    const int t    = threadIdx.x;
    const int obase = oc * (ODIM / 2);

    // stage xs[b] = sum of 4 partials (L2-resident), weights, bias
    {
        float4* s4 = reinterpret_cast<float4*>(s_xs);
        const float4* g4 = reinterpret_cast<const float4*>(g_part);
        for (int i = t; i < LDIM / 4; i += 256) {
            float4 a = g4[(0 * BDIM + b) * (LDIM / 4) + i];
            float4 c = g4[(1 * BDIM + b) * (LDIM / 4) + i];
            float4 d = g4[(2 * BDIM + b) * (LDIM / 4) + i];
            float4 e = g4[(3 * BDIM + b) * (LDIM / 4) + i];
            s4[i] = make_float4(a.x + c.x + d.x + e.x, a.y + c.y + d.y + e.y,
                                a.z + c.z + d.z + e.z, a.w + c.w + d.w + e.w);
        }
        for (int i = t; i < (ODIM / 2) * KDIM; i += 256)
            s_wc[i] = g_wcn[obase * KDIM + i];
        if (t < ODIM / 2) s_bias[t] = bias[obase + t];
    }
    __syncthreads();

    const int l = tile * 1024 + t * 4;
    const float evinv = g_evinv;
    float4 e4 = *reinterpret_cast<const float4*>(ev + l);
    const float ex = e4.x * evinv, ey = e4.y * evinv,
                ez = e4.z * evinv, ew = e4.w * evinv;

    // gather 9 neighbors per lane from smem, pre-scaled by ev[l]/||ev||
    float gx[KDIM], gy[KDIM], gz[KDIM], gw[KDIM];
#pragma unroll
    for (int k = 0; k < KDIM; ++k) {
        int4 id = *reinterpret_cast<const int4*>(idxm + k * LDIM + l);
        gx[k] = s_xs[id.x] * ex;
        gy[k] = s_xs[id.y] * ey;
        gz[k] = s_xs[id.z] * ez;
        gw[k] = s_xs[id.w] * ew;
    }

    float* outp = out + ((size_t)b * ODIM + obase) * LDIM + l;
#pragma unroll 4
    for (int o = 0; o < ODIM / 2; ++o) {
        const float bo = s_bias[o];
        float ax = bo, ay = bo, az = bo, aw = bo;
#pragma unroll
        for (int k = 0; k < KDIM; ++k) {
            const float w = s_wc[o * KDIM + k];  // smem broadcast
            ax = fmaf(w, gx[k], ax);
            ay = fmaf(w, gy[k], ay);
            az = fmaf(w, gz[k], az);
            aw = fmaf(w, gw[k], aw);
        }
        // streaming store: output is never re-read, keep it out of L2
        __stcs(reinterpret_cast<float4*>(outp + (size_t)o * LDIM),
               make_float4(ax, ay, az, aw));
    }
}

// ---------------------------------------------------------------------------
extern "C" void kernel_launch(void* const* d_in, const int* in_sizes, int n_in,
                              void* d_out, int out_size) {
    const float* x    = nullptr;
    const float* wc   = nullptr;
    const float* ev   = nullptr;
    const float* bias = nullptr;
    const int*   idxm = nullptr;

    for (int i = 0; i < n_in; ++i) {
        switch (in_sizes[i]) {
            case BDIM * CIN * LDIM: x    = (const float*)d_in[i]; break;  // 8388608
            case ODIM * KDIM:       wc   = (const float*)d_in[i]; break;  // 1152
            case LDIM:              ev   = (const float*)d_in[i]; break;  // 4096
            case ODIM:              bias = (const float*)d_in[i]; break;  // 128
            case KDIM * LDIM:       idxm = (const int*)  d_in[i]; break;  // 36864
            default: break;
        }
    }

    float* out = (float*)d_out;

    reduce_prep_kernel<<<BDIM * 4 * CCHUNKS + 1, 256>>>(x, wc, ev);
    gmconv_main_kernel<<<dim3(4, BDIM, 2), 256>>>(idxm, ev, bias, out);
}